// round 17
// baseline (speedup 1.0000x reference)
#include <cuda_runtime.h>
#include <cstddef>

// Fixed problem shape: K=64, N=1048576, NS=1024, B=1024
constexpr int   Kdim  = 64;
constexpr long  Nn    = 1048576;
constexpr int   NSs   = 1024;
constexpr int   Bseq  = 1024;
constexpr int   SPC   = 8;            // sequences per CTA (one warp)
constexpr int   CTAS  = Bseq / SPC;   // 128
constexpr int   TBLK  = 32;           // staging block == renorm period
constexpr int   NBLK  = NSs / TBLK;   // 32
constexpr float L2E   = 1.4426950408889634f;
constexpr float LN2   = 0.6931471805599453f;

constexpr int ROWW = 36;              // words per state-row (144B)
constexpr int BLKW = Kdim * ROWW;     // 2304 words per block
constexpr int SEQW = 2 * BLKW + 4;    // 4612 words per seq (double buffer)
constexpr int OFF_TP  = SPC * SEQW * 4;          // 147584
constexpr int OFF_LPI = OFF_TP + Kdim * Kdim * 4;// 163968
constexpr int OFF_LS  = OFF_LPI + 256;           // 164224
constexpr int SMEMSZ  = OFF_LS + 256;            // 164480

__device__ float    gPart[Bseq];
__device__ unsigned gDone;   // zero-init; finalizer resets

// ---------------------------------------------------------------------------
__device__ __forceinline__ float ex2f(float x) {
    float r; asm("ex2.approx.ftz.f32 %0, %1;" : "=f"(r) : "f"(x)); return r;
}
__device__ __forceinline__ float lg2f(float x) {
    float r; asm("lg2.approx.ftz.f32 %0, %1;" : "=f"(r) : "f"(x)); return r;
}
__device__ __forceinline__ float warp_sum(float v) {
#pragma unroll
    for (int o = 16; o > 0; o >>= 1) v += __shfl_xor_sync(0xffffffffu, v, o);
    return v;
}
__device__ __forceinline__ double warp_sum_d(double v) {
#pragma unroll
    for (int o = 16; o > 0; o >>= 1) v += __shfl_xor_sync(0xffffffffu, v, o);
    return v;
}
__device__ __forceinline__ unsigned pack_bf16x2(float lo, float hi) {
    unsigned r; asm("cvt.rn.bf16x2.f32 %0, %1, %2;" : "=r"(r) : "f"(hi), "f"(lo)); return r;
}
__device__ __forceinline__ float blo(unsigned u) { return __uint_as_float(u << 16); }
__device__ __forceinline__ float bhi(unsigned u) { return __uint_as_float(u & 0xffff0000u); }
__device__ __forceinline__ float bf16r(float x) { return blo(pack_bf16x2(x, 0.f)); }
__device__ __forceinline__ void cpasync16(void* dst, const void* src) {
    unsigned d = (unsigned)__cvta_generic_to_shared(dst);
    asm volatile("cp.async.ca.shared.global [%0], [%1], 16;" :: "r"(d), "l"(src));
}
template <int N> __device__ __forceinline__ void wait_group() {
    asm volatile("cp.async.wait_group %0;" :: "n"(N));
}
__device__ __forceinline__ void commit_group() {
    asm volatile("cp.async.commit_group;");
}
// D(16x8,f32) += A(16x16,bf16) x B(16x8,bf16); A rows 8-15 forced zero
__device__ __forceinline__ void mma8(float& d0, float& d1, float& d2, float& d3,
                                     unsigned aLo, unsigned aHi,
                                     unsigned b0, unsigned b1) {
    asm volatile(
        "mma.sync.aligned.m16n8k16.row.col.f32.bf16.bf16.f32 "
        "{%0,%1,%2,%3}, {%4,%5,%6,%7}, {%8,%9}, {%0,%1,%2,%3};"
        : "+f"(d0), "+f"(d1), "+f"(d2), "+f"(d3)
        : "r"(aLo), "r"(0u), "r"(aHi), "r"(0u), "r"(b0), "r"(b1));
}

// stage one 32-step block (64 rows x 32 floats) of one sequence (no commit)
__device__ __forceinline__ void issue_stage(float* sbuf, const float* gbase, int l) {
#pragma unroll
    for (int i = 0; i < 16; i++) {
        int m   = (i << 5) + l;
        int row = m >> 3;
        int c4  = (m & 7) << 2;
        cpasync16(sbuf + row * ROWW + c4, gbase + (size_t)row * Nn + c4);
    }
}

// ---------------------------------------------------------------------------
// fully register-resident tensor-core forward scan: 128 single-warp CTAs,
// each warp owns 8 sequences; q never leaves registers (D->A fragment identity)
// ---------------------------------------------------------------------------
__global__ void __launch_bounds__(32) fwd_kernel(const float* __restrict__ lp,
                                                 const float* __restrict__ pi,
                                                 const float* __restrict__ T,
                                                 float* __restrict__ out) {
    extern __shared__ char dsm[];
    float* stf  = (float*)dsm;
    float* sTp  = (float*)(dsm + OFF_TP);
    float* sLpi = (float*)(dsm + OFF_LPI);
    float* sLs  = (float*)(dsm + OFF_LS);

    const int l  = threadIdx.x;
    const int g  = l >> 2;              // seq (fragment row group)
    const int c  = l & 3;               // fragment col group
    const int bb = blockIdx.x * SPC;

    // stage blocks 0 and 1 for all 8 sequences (two commit groups)
#pragma unroll 1
    for (int s2 = 0; s2 < SPC; s2++)
        issue_stage(stf + s2 * SEQW, lp + (size_t)(bb + s2) * NSs, l);
    commit_group();
#pragma unroll 1
    for (int s2 = 0; s2 < SPC; s2++)
        issue_stage(stf + s2 * SEQW + BLKW, lp + (size_t)(bb + s2) * NSs + TBLK, l);
    commit_group();

    // ---- prep (per CTA, one warp): softmax rows of T ----
#pragma unroll 1
    for (int r = 0; r < Kdim; r++) {
        float a = T[r * Kdim + l], cc = T[r * Kdim + l + 32];
        float m = fmaxf(a, cc);
#pragma unroll
        for (int o = 16; o > 0; o >>= 1) m = fmaxf(m, __shfl_xor_sync(0xffffffffu, m, o));
        float ea = expf(a - m), ec = expf(cc - m);
        float ss = warp_sum(ea + ec);
        float inv = 1.0f / ss;
        sTp[r * Kdim + l]      = ea * inv;
        sTp[r * Kdim + l + 32] = ec * inv;
    }
    __syncwarp();
    {   // log_softmax(pi) * log2e
        float pa = pi[l], pb = pi[l + 32];
        float m2 = fmaxf(pa, pb);
#pragma unroll
        for (int o = 16; o > 0; o >>= 1) m2 = fmaxf(m2, __shfl_xor_sync(0xffffffffu, m2, o));
        float sp = warp_sum(expf(pa - m2) + expf(pb - m2));
        float ls = logf(sp);
        sLpi[l]      = (pa - m2 - ls) * L2E;
        sLpi[l + 32] = (pb - m2 - ls) * L2E;
    }
    {   // stationary distribution (6 iters) + bf16(T) bias correction
        float wA = 1.0f / 64.0f, wB = 1.0f / 64.0f;
#pragma unroll 1
        for (int it = 0; it < 6; it++) {
            float nA = 0.f, nBv = 0.f;
#pragma unroll 4
            for (int j = 0; j < 32; j++) {
                float wj0 = __shfl_sync(0xffffffffu, wA, j);
                float wj1 = __shfl_sync(0xffffffffu, wB, j);
                nA  = fmaf(wj0, sTp[(2 * j) * Kdim + 2 * l],     nA);
                nA  = fmaf(wj1, sTp[(2 * j + 1) * Kdim + 2 * l], nA);
                nBv = fmaf(wj0, sTp[(2 * j) * Kdim + 2 * l + 1],     nBv);
                nBv = fmaf(wj1, sTp[(2 * j + 1) * Kdim + 2 * l + 1], nBv);
            }
            float S = warp_sum(nA + nBv);
            wA = nA / S; wB = nBv / S;
        }
        float nA = 0.f, nBv = 0.f, dA = 0.f, dB = 0.f;
#pragma unroll 4
        for (int j = 0; j < 32; j++) {
            float wj0 = __shfl_sync(0xffffffffu, wA, j);
            float wj1 = __shfl_sync(0xffffffffu, wB, j);
            float t00 = sTp[(2 * j) * Kdim + 2 * l];
            float t10 = sTp[(2 * j + 1) * Kdim + 2 * l];
            float t01 = sTp[(2 * j) * Kdim + 2 * l + 1];
            float t11 = sTp[(2 * j + 1) * Kdim + 2 * l + 1];
            nA  += wj0 * t00 + wj1 * t10;
            nBv += wj0 * t01 + wj1 * t11;
            dA  += wj0 * bf16r(t00) + wj1 * bf16r(t10);
            dB  += wj0 * bf16r(t01) + wj1 * bf16r(t11);
        }
        sLs[2 * l]     = log2f(nA / dA);
        sLs[2 * l + 1] = log2f(nBv / dB);
    }
    __syncwarp();

    // ---- B fragments: full T resident in 64 registers ----
    // n-tile w, k-chunk kc: b0={T[16kc+2c][8w+g], T[16kc+2c+1][..]}, b1 = rows +8
    unsigned B0[32], B1[32];
#pragma unroll
    for (int w = 0; w < 8; w++) {
        int n = 8 * w + g;
#pragma unroll
        for (int kc = 0; kc < 4; kc++) {
            int kb = 16 * kc + 2 * c;
            B0[4 * w + kc] = pack_bf16x2(sTp[kb * Kdim + n],       sTp[(kb + 1) * Kdim + n]);
            B1[4 * w + kc] = pack_bf16x2(sTp[(kb + 8) * Kdim + n], sTp[(kb + 9) * Kdim + n]);
        }
    }
    float ls0[8], ls1[8];
#pragma unroll
    for (int w = 0; w < 8; w++) { ls0[w] = sLs[8 * w + 2 * c]; ls1[w] = sLs[8 * w + 2 * c + 1]; }

    wait_group<1>();
    __syncwarp();

    // ---- t = 0 init: q = exp2(lp0*log2e + log2_pi), packed straight into A frags
    const float* eb = stf + g * SEQW + 2 * c * ROWW;   // + (8w)*ROWW per tile
    unsigned Af0[4], Af2[4];
#pragma unroll
    for (int w = 0; w < 8; w++) {
        float e0 = eb[(8 * w) * ROWW];
        float e1 = eb[(8 * w + 1) * ROWW];
        float q0 = ex2f(fmaf(e0, L2E, sLpi[8 * w + 2 * c]));
        float q1 = ex2f(fmaf(e1, L2E, sLpi[8 * w + 2 * c + 1]));
        unsigned pk = pack_bf16x2(q0, q1);
        if (w & 1) Af2[w >> 1] = pk; else Af0[w >> 1] = pk;
    }

    double cacc = 0.0;
    float  gp   = 0.0f;

#pragma unroll 1
    for (int t = 1; t < NSs; t++) {
        if ((t & (TBLK - 1)) == 0) {
            int k = t >> 5;
            if (k < NBLK - 1) {
#pragma unroll 1
                for (int s2 = 0; s2 < SPC; s2++)
                    issue_stage(stf + s2 * SEQW + ((k + 1) & 1) * BLKW,
                                lp + (size_t)(bb + s2) * NSs + (size_t)(k + 1) * TBLK, l);
                commit_group();
            }
            // renorm from packed q (scale estimate; accounting exact)
            float S = 0.f;
#pragma unroll
            for (int kc = 0; kc < 4; kc++)
                S += (blo(Af0[kc]) + bhi(Af0[kc])) + (blo(Af2[kc]) + bhi(Af2[kc]));
            S += __shfl_xor_sync(0xffffffffu, S, 1);
            S += __shfl_xor_sync(0xffffffffu, S, 2);
            float gg = lg2f(S);
            cacc += (double)gg;
            gp = -gg;
            if (k < NBLK - 1) wait_group<1>(); else wait_group<0>();
            __syncwarp();
        }
        const float* sb = stf + g * SEQW + ((t >> 5) & 1) * BLKW + (t & (TBLK - 1))
                        + 2 * c * ROWW;

        // f factors (off the MMA chain)
        float f0[8], f1[8];
#pragma unroll
        for (int w = 0; w < 8; w++) {
            float e0 = sb[(8 * w) * ROWW];
            float e1 = sb[(8 * w + 1) * ROWW];
            f0[w] = ex2f(fmaf(e0, L2E, ls0[w] + gp));
            f1[w] = ex2f(fmaf(e1, L2E, ls1[w] + gp));
        }
        gp = 0.0f;

        unsigned nAf0[4], nAf2[4];
#pragma unroll
        for (int w = 0; w < 8; w++) {
            float d0 = 0.f, d1 = 0.f, d2 = 0.f, d3 = 0.f;
            float h0 = 0.f, h1 = 0.f, h2 = 0.f, h3 = 0.f;
            mma8(d0, d1, d2, d3, Af0[0], Af2[0], B0[4 * w + 0], B1[4 * w + 0]);
            mma8(d0, d1, d2, d3, Af0[1], Af2[1], B0[4 * w + 1], B1[4 * w + 1]);
            mma8(h0, h1, h2, h3, Af0[2], Af2[2], B0[4 * w + 2], B1[4 * w + 2]);
            mma8(h0, h1, h2, h3, Af0[3], Af2[3], B0[4 * w + 3], B1[4 * w + 3]);
            float q0 = f0[w] * (d0 + h0);
            float q1 = f1[w] * (d1 + h1);
            unsigned pk = pack_bf16x2(q0, q1);
            if (w & 1) nAf2[w >> 1] = pk; else nAf0[w >> 1] = pk;
        }
#pragma unroll
        for (int kc = 0; kc < 4; kc++) { Af0[kc] = nAf0[kc]; Af2[kc] = nAf2[kc]; }
    }

    // ---- final per-seq log-likelihoods ----
    {
        float S = 0.f;
#pragma unroll
        for (int kc = 0; kc < 4; kc++)
            S += (blo(Af0[kc]) + bhi(Af0[kc])) + (blo(Af2[kc]) + bhi(Af2[kc]));
        S += __shfl_xor_sync(0xffffffffu, S, 1);
        S += __shfl_xor_sync(0xffffffffu, S, 2);
        if ((l & 3) == 0)
            gPart[bb + g] = LN2 * (float)(cacc + (double)lg2f(S));
    }

    // ---- fused deterministic final reduction (last CTA) ----
    __threadfence();
    unsigned rank = 0;
    if (l == 0) rank = atomicAdd(&gDone, 1u);
    rank = __shfl_sync(0xffffffffu, rank, 0);
    if (rank == CTAS - 1) {
        __threadfence();
        double v = 0.0;
        for (int i = l; i < Bseq; i += 32) v += (double)gPart[i];  // fixed order
        v = warp_sum_d(v);                                          // fixed tree
        if (l == 0) {
            out[0] = (float)v;
            gDone = 0u;   // reset for next graph replay
        }
    }
}

// ---------------------------------------------------------------------------
extern "C" void kernel_launch(void* const* d_in, const int* in_sizes, int n_in,
                              void* d_out, int out_size) {
    const float* lp = (const float*)d_in[0];  // log_pdf (K, N)
    const float* pi = (const float*)d_in[1];  // pi (K,)
    const float* T  = (const float*)d_in[2];  // T (K, K)
    (void)in_sizes; (void)n_in; (void)out_size;

    cudaFuncSetAttribute(fwd_kernel, cudaFuncAttributeMaxDynamicSharedMemorySize, SMEMSZ);
    fwd_kernel<<<CTAS, 32, SMEMSZ>>>(lp, pi, T, (float*)d_out);
}